// round 6
// baseline (speedup 1.0000x reference)
#include <cuda_runtime.h>
#include <math.h>

#define H 4096
#define S 4096
#define NROWS (3 * H)   // 12288 rows per weight matrix
#define NCHUNK 32       // act/scan chunks (H / 128)

// Scratch (allocation-free rule: __device__ globals)
__device__ float g_y_ih[NROWS];
__device__ float g_y_hh[NROWS];
__device__ float g_P[S];         // chunk-local inclusive prefix of a[]
__device__ float g_bsum[NCHUNK];
__device__ float g_boff[NCHUNK]; // exclusive prefix of chunk sums

// ---------------------------------------------------------------------------
// Kernel 1: fused dual GEMV, one warp per row, 16 rows / 512-thread block.
// Two independent fma chains keep the per-warp dependency chain off the
// critical path; __ldcs keeps 402 MB of read-once weights out of L2's way.
// ---------------------------------------------------------------------------
__global__ void __launch_bounds__(512) gemv_kernel(
    const float* __restrict__ x, const float* __restrict__ hidden,
    const float* __restrict__ w_ih, const float* __restrict__ w_hh,
    const float* __restrict__ b_ih, const float* __restrict__ b_hh)
{
    __shared__ float4 vs[H / 4];   // 16 KB

    const int rowBase = blockIdx.x * 16;
    const bool isIH = rowBase < NROWS;   // blocks never straddle: 12288 % 16 == 0

    const float* vec = isIH ? x : hidden;
    for (int i = threadIdx.x; i < H / 4; i += blockDim.x)
        vs[i] = reinterpret_cast<const float4*>(vec)[i];
    __syncthreads();

    const int warp = threadIdx.x >> 5;
    const int lane = threadIdx.x & 31;
    const int r    = rowBase + warp;
    const int lr   = isIH ? r : (r - NROWS);

    const float* W    = isIH ? w_ih : w_hh;
    const float* bias = isIH ? b_ih : b_hh;
    float*       yout = isIH ? g_y_ih : g_y_hh;

    const float4* wrow = reinterpret_cast<const float4*>(W + (size_t)lr * H);

    float acc0 = 0.0f, acc1 = 0.0f;
#pragma unroll 4
    for (int i = lane; i < H / 4; i += 64) {
        float4 wa = __ldcs(&wrow[i]);
        float4 wb = __ldcs(&wrow[i + 32]);
        float4 va = vs[i];
        float4 vb = vs[i + 32];
        acc0 = fmaf(wa.x, va.x, acc0);
        acc0 = fmaf(wa.y, va.y, acc0);
        acc0 = fmaf(wa.z, va.z, acc0);
        acc0 = fmaf(wa.w, va.w, acc0);
        acc1 = fmaf(wb.x, vb.x, acc1);
        acc1 = fmaf(wb.y, vb.y, acc1);
        acc1 = fmaf(wb.z, vb.z, acc1);
        acc1 = fmaf(wb.w, vb.w, acc1);
    }
    float acc = acc0 + acc1;
#pragma unroll
    for (int off = 16; off > 0; off >>= 1)
        acc += __shfl_down_sync(0xffffffffu, acc, off);

    if (lane == 0)
        yout[lr] = acc + bias[lr];
}

// ---------------------------------------------------------------------------
// Kernel 2a: GRU elementwise + chunk-local inclusive scan (32 x 128).
// ---------------------------------------------------------------------------
__global__ void __launch_bounds__(128) act_kernel(const float* __restrict__ hidden)
{
    __shared__ float warp_sums[4];

    const int tid  = threadIdx.x;
    const int lane = tid & 31;
    const int wid  = tid >> 5;
    const int j    = blockIdx.x * 128 + tid;

    const float i_r = g_y_ih[j];
    const float i_z = g_y_ih[j + H];
    const float i_n = g_y_ih[j + 2 * H];
    const float h_r = g_y_hh[j];
    const float h_z = g_y_hh[j + H];
    const float h_n = g_y_hh[j + 2 * H];

    const float rg = 1.0f / (1.0f + __expf(-(i_r + h_r)));
    const float zg = 1.0f / (1.0f + __expf(-(i_z + h_z)));
    const float ng = tanhf(i_n + rg * h_n);
    const float b  = (1.0f - zg) * hidden[j] + zg * ng;
    float a = fmaxf(b, 0.0f);

    float t = a;
#pragma unroll
    for (int off = 1; off < 32; off <<= 1) {
        float n = __shfl_up_sync(0xffffffffu, t, off);
        if (lane >= off) t += n;
    }
    if (lane == 31) warp_sums[wid] = t;
    __syncthreads();

    float base = 0.0f;
#pragma unroll
    for (int w = 0; w < 4; w++)
        if (w < wid) base += warp_sums[w];

    g_P[j] = base + t;
    if (tid == 127)
        g_bsum[blockIdx.x] = base + t;
}

// ---------------------------------------------------------------------------
// Kernel 2b: one warp scans 32 chunk sums into exclusive offsets.
// ---------------------------------------------------------------------------
__global__ void scan_sums_kernel()
{
    const int lane = threadIdx.x;
    const float v = g_bsum[lane];
    float t = v;
#pragma unroll
    for (int off = 1; off < 32; off <<= 1) {
        float n = __shfl_up_sync(0xffffffffu, t, off);
        if (lane >= off) t += n;
    }
    g_boff[lane] = t - v;   // exclusive
}

// ---------------------------------------------------------------------------
// Kernel 3: outputs[t][j] = P[t] + hidden[(j - t - 1) mod H].
// 4 rows per 256-thread block. The 4 rows need hidden at shifts off0..off0-3,
// i.e. 7 consecutive floats per j-group: load a 12-float ALIGNED window with
// 3x LDG.128 and assemble all four output float4s in registers. The
// misalignment phase d = s & 3 is block-uniform -> static-index branches.
// ---------------------------------------------------------------------------
template <int D>
__device__ __forceinline__ void emit_rows(
    const float f[12], const float p[4], float* __restrict__ out,
    size_t rowStride, int j4, int t0, int write_tail, float* __restrict__ tail)
{
#pragma unroll
    for (int r = 0; r < 4; r++) {
        float4 v;
        v.x = p[r] + f[D + 3 - r + 0];
        v.y = p[r] + f[D + 3 - r + 1];
        v.z = p[r] + f[D + 3 - r + 2];
        v.w = p[r] + f[D + 3 - r + 3];
        reinterpret_cast<float4*>(out + (size_t)(t0 + r) * rowStride)[j4] = v;
        if (write_tail && (t0 + r) == S - 1)
            reinterpret_cast<float4*>(tail)[j4] = v;
    }
}

__global__ void __launch_bounds__(256) write_kernel(
    const float* __restrict__ hidden, float* __restrict__ out, int write_tail)
{
    const int t0   = blockIdx.x * 4;
    const int off0 = H - 1 - t0;            // in [3, 4095]
    const int d    = (off0 - 3) & 3;        // block-uniform phase (j is 4-aligned)

    float p[4];
#pragma unroll
    for (int r = 0; r < 4; r++)
        p[r] = g_P[t0 + r] + g_boff[(t0 + r) >> 7];

    float* tail = out + (size_t)S * H;

#pragma unroll
    for (int it = 0; it < (H / 4) / 256; it++) {   // 4 iterations
        const int j4 = it * 256 + threadIdx.x;
        const int j  = j4 * 4;
        const int s  = j + off0 - 3;               // >= 0
        const int a0 = s & ~3;

        float f[12];
        float4 f0 = __ldg(reinterpret_cast<const float4*>(hidden + ((a0)     & (H - 1))));
        float4 f1 = __ldg(reinterpret_cast<const float4*>(hidden + ((a0 + 4) & (H - 1))));
        float4 f2 = __ldg(reinterpret_cast<const float4*>(hidden + ((a0 + 8) & (H - 1))));
        f[0] = f0.x; f[1]  = f0.y; f[2]  = f0.z; f[3]  = f0.w;
        f[4] = f1.x; f[5]  = f1.y; f[6]  = f1.z; f[7]  = f1.w;
        f[8] = f2.x; f[9]  = f2.y; f[10] = f2.z; f[11] = f2.w;

        switch (d) {
            case 0: emit_rows<0>(f, p, out, H, j4, t0, write_tail, tail); break;
            case 1: emit_rows<1>(f, p, out, H, j4, t0, write_tail, tail); break;
            case 2: emit_rows<2>(f, p, out, H, j4, t0, write_tail, tail); break;
            default: emit_rows<3>(f, p, out, H, j4, t0, write_tail, tail); break;
        }
    }
}

extern "C" void kernel_launch(void* const* d_in, const int* in_sizes, int n_in,
                              void* d_out, int out_size)
{
    const float* x      = (const float*)d_in[0];
    const float* hidden = (const float*)d_in[1];
    const float* w_ih   = (const float*)d_in[2];
    const float* w_hh   = (const float*)d_in[3];
    const float* b_ih   = (const float*)d_in[4];
    const float* b_hh   = (const float*)d_in[5];
    float* out = (float*)d_out;

    const int write_tail = ((long long)out_size - (long long)S * H) >= H ? 1 : 0;

    gemv_kernel<<<(2 * NROWS) / 16, 512>>>(x, hidden, w_ih, w_hh, b_ih, b_hh);
    act_kernel<<<NCHUNK, 128>>>(hidden);
    scan_sums_kernel<<<1, 32>>>();
    write_kernel<<<S / 4, 256>>>(hidden, out, write_tail);
}

// round 8
// speedup vs baseline: 1.0207x; 1.0207x over previous
#include <cuda_runtime.h>
#include <math.h>

#define H 4096
#define S 4096
#define NROWS (3 * H)   // 12288 rows per weight matrix
#define NCHUNK 32       // act/scan chunks (H / 128)

// Scratch (allocation-free rule: __device__ globals)
__device__ float g_y_ih[NROWS];
__device__ float g_y_hh[NROWS];
__device__ float g_P[S];         // chunk-local inclusive prefix of a[]
__device__ float g_bsum[NCHUNK];
__device__ float g_boff[NCHUNK]; // exclusive prefix of chunk sums

// ---------------------------------------------------------------------------
// Kernel 1: fused dual GEMV, one warp per row, 16 rows / 512-thread block.
// Single fma chain, unroll 8 (best measured: 65.6us / 6.2 TB/s).
// __ldcs keeps 402 MB of read-once weights from thrashing L2.
// ---------------------------------------------------------------------------
__global__ void __launch_bounds__(512) gemv_kernel(
    const float* __restrict__ x, const float* __restrict__ hidden,
    const float* __restrict__ w_ih, const float* __restrict__ w_hh,
    const float* __restrict__ b_ih, const float* __restrict__ b_hh)
{
    __shared__ float4 vs[H / 4];   // 16 KB

    const int rowBase = blockIdx.x * 16;
    const bool isIH = rowBase < NROWS;   // blocks never straddle: 12288 % 16 == 0

    const float* vec = isIH ? x : hidden;
    for (int i = threadIdx.x; i < H / 4; i += blockDim.x)
        vs[i] = reinterpret_cast<const float4*>(vec)[i];
    __syncthreads();

    const int warp = threadIdx.x >> 5;
    const int lane = threadIdx.x & 31;
    const int r    = rowBase + warp;
    const int lr   = isIH ? r : (r - NROWS);

    const float* W    = isIH ? w_ih : w_hh;
    const float* bias = isIH ? b_ih : b_hh;
    float*       yout = isIH ? g_y_ih : g_y_hh;

    const float4* wrow = reinterpret_cast<const float4*>(W + (size_t)lr * H);

    float acc = 0.0f;
#pragma unroll 8
    for (int i = lane; i < H / 4; i += 32) {
        float4 w4 = __ldcs(&wrow[i]);
        float4 v4 = vs[i];
        acc = fmaf(w4.x, v4.x, acc);
        acc = fmaf(w4.y, v4.y, acc);
        acc = fmaf(w4.z, v4.z, acc);
        acc = fmaf(w4.w, v4.w, acc);
    }
#pragma unroll
    for (int off = 16; off > 0; off >>= 1)
        acc += __shfl_down_sync(0xffffffffu, acc, off);

    if (lane == 0)
        yout[lr] = acc + bias[lr];
}

// ---------------------------------------------------------------------------
// Kernel 2a: GRU elementwise + chunk-local inclusive scan (32 x 128).
// ---------------------------------------------------------------------------
__global__ void __launch_bounds__(128) act_kernel(const float* __restrict__ hidden)
{
    __shared__ float warp_sums[4];

    const int tid  = threadIdx.x;
    const int lane = tid & 31;
    const int wid  = tid >> 5;
    const int j    = blockIdx.x * 128 + tid;

    const float i_r = g_y_ih[j];
    const float i_z = g_y_ih[j + H];
    const float i_n = g_y_ih[j + 2 * H];
    const float h_r = g_y_hh[j];
    const float h_z = g_y_hh[j + H];
    const float h_n = g_y_hh[j + 2 * H];

    const float rg = 1.0f / (1.0f + __expf(-(i_r + h_r)));
    const float zg = 1.0f / (1.0f + __expf(-(i_z + h_z)));
    const float ng = tanhf(i_n + rg * h_n);
    const float b  = (1.0f - zg) * hidden[j] + zg * ng;
    float a = fmaxf(b, 0.0f);

    float t = a;
#pragma unroll
    for (int off = 1; off < 32; off <<= 1) {
        float n = __shfl_up_sync(0xffffffffu, t, off);
        if (lane >= off) t += n;
    }
    if (lane == 31) warp_sums[wid] = t;
    __syncthreads();

    float base = 0.0f;
#pragma unroll
    for (int w = 0; w < 4; w++)
        if (w < wid) base += warp_sums[w];

    g_P[j] = base + t;
    if (tid == 127)
        g_bsum[blockIdx.x] = base + t;
}

// ---------------------------------------------------------------------------
// Kernel 2b: one warp scans 32 chunk sums into exclusive offsets.
// ---------------------------------------------------------------------------
__global__ void scan_sums_kernel()
{
    const int lane = threadIdx.x;
    const float v = g_bsum[lane];
    float t = v;
#pragma unroll
    for (int off = 1; off < 32; off <<= 1) {
        float n = __shfl_up_sync(0xffffffffu, t, off);
        if (lane >= off) t += n;
    }
    g_boff[lane] = t - v;   // exclusive
}

// ---------------------------------------------------------------------------
// Kernel 3: outputs[t][j] = P[t] + hidden[(j - t - 1) mod H].
// 8 rows per 256-thread block. The 8 rows need hidden at shifts
// off0 .. off0-7, i.e. 11 consecutive floats per j-group: load a 16-float
// ALIGNED window (4x LDG.128, mod H per quad) and assemble all eight output
// float4s from registers. Phase d = s & 3 is block-uniform.
// ---------------------------------------------------------------------------
template <int D>
__device__ __forceinline__ void emit_rows8(
    const float f[16], const float p[8], float* __restrict__ out,
    int j4, int t0, int write_tail, float* __restrict__ tail)
{
#pragma unroll
    for (int r = 0; r < 8; r++) {
        float4 v;
        v.x = p[r] + f[D + 7 - r + 0];
        v.y = p[r] + f[D + 7 - r + 1];
        v.z = p[r] + f[D + 7 - r + 2];
        v.w = p[r] + f[D + 7 - r + 3];
        reinterpret_cast<float4*>(out + (size_t)(t0 + r) * H)[j4] = v;
        if (write_tail && (t0 + r) == S - 1)
            reinterpret_cast<float4*>(tail)[j4] = v;
    }
}

__global__ void __launch_bounds__(256) write_kernel(
    const float* __restrict__ hidden, float* __restrict__ out, int write_tail)
{
    const int t0   = blockIdx.x * 8;
    const int off0 = H - 1 - t0;            // in [7, 4095]
    const int d    = (off0 - 7) & 3;        // block-uniform phase (j is 4-aligned)

    float p[8];
#pragma unroll
    for (int r = 0; r < 8; r++)
        p[r] = g_P[t0 + r] + g_boff[(t0 + r) >> 7];

    float* tail = out + (size_t)S * H;

#pragma unroll
    for (int it = 0; it < (H / 4) / 256; it++) {   // 4 iterations
        const int j4 = it * 256 + threadIdx.x;
        const int j  = j4 * 4;
        const int s  = j + off0 - 7;               // >= 0
        const int a0 = s & ~3;

        float f[16];
        float4 f0 = __ldg(reinterpret_cast<const float4*>(hidden + ((a0)      & (H - 1))));
        float4 f1 = __ldg(reinterpret_cast<const float4*>(hidden + ((a0 + 4)  & (H - 1))));
        float4 f2 = __ldg(reinterpret_cast<const float4*>(hidden + ((a0 + 8)  & (H - 1))));
        float4 f3 = __ldg(reinterpret_cast<const float4*>(hidden + ((a0 + 12) & (H - 1))));
        f[0]  = f0.x; f[1]  = f0.y; f[2]  = f0.z; f[3]  = f0.w;
        f[4]  = f1.x; f[5]  = f1.y; f[6]  = f1.z; f[7]  = f1.w;
        f[8]  = f2.x; f[9]  = f2.y; f[10] = f2.z; f[11] = f2.w;
        f[12] = f3.x; f[13] = f3.y; f[14] = f3.z; f[15] = f3.w;

        switch (d) {
            case 0: emit_rows8<0>(f, p, out, j4, t0, write_tail, tail); break;
            case 1: emit_rows8<1>(f, p, out, j4, t0, write_tail, tail); break;
            case 2: emit_rows8<2>(f, p, out, j4, t0, write_tail, tail); break;
            default: emit_rows8<3>(f, p, out, j4, t0, write_tail, tail); break;
        }
    }
}

extern "C" void kernel_launch(void* const* d_in, const int* in_sizes, int n_in,
                              void* d_out, int out_size)
{
    const float* x      = (const float*)d_in[0];
    const float* hidden = (const float*)d_in[1];
    const float* w_ih   = (const float*)d_in[2];
    const float* w_hh   = (const float*)d_in[3];
    const float* b_ih   = (const float*)d_in[4];
    const float* b_hh   = (const float*)d_in[5];
    float* out = (float*)d_out;

    const int write_tail = ((long long)out_size - (long long)S * H) >= H ? 1 : 0;

    gemv_kernel<<<(2 * NROWS) / 16, 512>>>(x, hidden, w_ih, w_hh, b_ih, b_hh);
    act_kernel<<<NCHUNK, 128>>>(hidden);
    scan_sums_kernel<<<1, 32>>>();
    write_kernel<<<S / 8, 256>>>(hidden, out, write_tail);
}